// round 2
// baseline (speedup 1.0000x reference)
#include <cuda_runtime.h>

#define NN 100000
#define EE 1600000
#define C  128
#define NG 64
#define OUTC 10

// ---------------- scratch (static __device__, no allocs) ----------------
__device__ float g_bufA[(size_t)NN * C];   // y = dinv * (x@W)
__device__ float g_bufB[(size_t)NN * C];   // h
__device__ float g_dinv[NN];
__device__ int   g_cnt[NN];
__device__ int   g_rowoff[NN + 1];
__device__ int   g_cursor[NN];
__device__ int   g_csr[EE];
__device__ float g_pool[NG * C];
__device__ float g_gcnt[NG];

// ---------------- zero scratch ----------------
__global__ void k_zero() {
    int i = blockIdx.x * blockDim.x + threadIdx.x;
    int stride = gridDim.x * blockDim.x;
    for (int j = i; j < NN; j += stride) g_cnt[j] = 0;
    if (i < NG * C) g_pool[i] = 0.f;
    if (i < NG)     g_gcnt[i] = 0.f;
}

// ---------------- in-degree histogram over dst (int32 indices!) ----------------
__global__ void k_hist(const int* __restrict__ dst) {
    int i = blockIdx.x * blockDim.x + threadIdx.x;
    int stride = gridDim.x * blockDim.x;
    for (int e = i; e < EE; e += stride)
        atomicAdd(&g_cnt[dst[e]], 1);
}

// ---------------- exclusive scan + dinv (+1 self loop) ----------------
__global__ void k_scan() {
    __shared__ int wsum[32];
    __shared__ int s_total;
    int tid = threadIdx.x, lane = tid & 31, wid = tid >> 5;
    int carry = 0;
    for (int base = 0; base < NN; base += 1024) {
        int i = base + tid;
        int v = (i < NN) ? g_cnt[i] : 0;
        int x = v;
        #pragma unroll
        for (int o = 1; o < 32; o <<= 1) {
            int t = __shfl_up_sync(0xffffffffu, x, o);
            if (lane >= o) x += t;
        }
        if (lane == 31) wsum[wid] = x;
        __syncthreads();
        if (wid == 0) {
            int w = wsum[lane];
            int y = w;
            #pragma unroll
            for (int o = 1; o < 32; o <<= 1) {
                int t = __shfl_up_sync(0xffffffffu, y, o);
                if (lane >= o) y += t;
            }
            wsum[lane] = y - w;   // exclusive warp prefix
        }
        __syncthreads();
        int incl = x + wsum[wid];
        int excl = carry + incl - v;
        if (i < NN) {
            g_rowoff[i] = excl;
            g_cursor[i] = excl;
            g_dinv[i] = rsqrtf((float)(v + 1));
        }
        if (tid == 1023) s_total = incl;
        __syncthreads();
        carry += s_total;
        __syncthreads();
    }
    if (tid == 0) g_rowoff[NN] = carry;
}

// ---------------- scatter edges into CSR buckets ----------------
__global__ void k_fill(const int* __restrict__ src,
                       const int* __restrict__ dst) {
    int i = blockIdx.x * blockDim.x + threadIdx.x;
    int stride = gridDim.x * blockDim.x;
    for (int e = i; e < EE; e += stride) {
        int d = dst[e];
        int pos = atomicAdd(&g_cursor[d], 1);
        g_csr[pos] = src[e];
    }
}

// ---------------- GEMM: Y[m] = scale[m] * (A[m] @ W), 128x128 tile ----------------
__global__ __launch_bounds__(256, 2)
void k_gemm(const float* __restrict__ A, const float* __restrict__ W,
            float* __restrict__ Y, const float* __restrict__ scale, int M) {
    __shared__ float As[8][132];
    __shared__ float Bs[8][128];
    int tid = threadIdx.x;
    int m0 = blockIdx.x * 128;
    int tx = tid & 15, ty = tid >> 4;
    float acc[8][8];
    #pragma unroll
    for (int i = 0; i < 8; i++)
        #pragma unroll
        for (int j = 0; j < 8; j++) acc[i][j] = 0.f;

    int la_m = tid >> 1, la_k = (tid & 1) * 4;
    int lb_k = tid >> 5, lb_n = (tid & 31) * 4;
    int gm_l = m0 + la_m;

    for (int k0 = 0; k0 < C; k0 += 8) {
        float4 av = make_float4(0.f, 0.f, 0.f, 0.f);
        if (gm_l < M) av = *(const float4*)&A[(size_t)gm_l * C + k0 + la_k];
        As[la_k + 0][la_m] = av.x;
        As[la_k + 1][la_m] = av.y;
        As[la_k + 2][la_m] = av.z;
        As[la_k + 3][la_m] = av.w;
        *(float4*)&Bs[lb_k][lb_n] = *(const float4*)&W[(size_t)(k0 + lb_k) * C + lb_n];
        __syncthreads();
        #pragma unroll
        for (int kk = 0; kk < 8; kk++) {
            float a[8], b[8];
            #pragma unroll
            for (int i = 0; i < 8; i++) a[i] = As[kk][ty * 8 + i];
            #pragma unroll
            for (int j = 0; j < 8; j++) b[j] = Bs[kk][tx * 8 + j];
            #pragma unroll
            for (int i = 0; i < 8; i++)
                #pragma unroll
                for (int j = 0; j < 8; j++)
                    acc[i][j] = fmaf(a[i], b[j], acc[i][j]);
        }
        __syncthreads();
    }

    #pragma unroll
    for (int i = 0; i < 8; i++) {
        int gm = m0 + ty * 8 + i;
        if (gm < M) {
            float s = scale ? scale[gm] : 1.f;
            float4 o0, o1;
            o0.x = acc[i][0] * s; o0.y = acc[i][1] * s;
            o0.z = acc[i][2] * s; o0.w = acc[i][3] * s;
            o1.x = acc[i][4] * s; o1.y = acc[i][5] * s;
            o1.z = acc[i][6] * s; o1.w = acc[i][7] * s;
            *(float4*)&Y[(size_t)gm * C + tx * 8]     = o0;
            *(float4*)&Y[(size_t)gm * C + tx * 8 + 4] = o1;
        }
    }
}

// ---------------- aggregation: warp per dst node, pure gather ----------------
__global__ __launch_bounds__(256)
void k_agg(const float* __restrict__ Y, float* __restrict__ H,
           const float* __restrict__ bias) {
    int t = blockIdx.x * blockDim.x + threadIdx.x;
    int d = t >> 5;
    if (d >= NN) return;
    int lane = t & 31;
    const float4* Yv = (const float4*)Y;

    float4 acc = Yv[(size_t)d * 32 + lane];   // self loop term
    int e = g_rowoff[d], end = g_rowoff[d + 1];

    for (; e + 4 <= end; e += 4) {
        int s0 = g_csr[e], s1 = g_csr[e + 1], s2 = g_csr[e + 2], s3 = g_csr[e + 3];
        float4 v0 = Yv[(size_t)s0 * 32 + lane];
        float4 v1 = Yv[(size_t)s1 * 32 + lane];
        float4 v2 = Yv[(size_t)s2 * 32 + lane];
        float4 v3 = Yv[(size_t)s3 * 32 + lane];
        acc.x += (v0.x + v1.x) + (v2.x + v3.x);
        acc.y += (v0.y + v1.y) + (v2.y + v3.y);
        acc.z += (v0.z + v1.z) + (v2.z + v3.z);
        acc.w += (v0.w + v1.w) + (v2.w + v3.w);
    }
    for (; e < end; e++) {
        int s = g_csr[e];
        float4 v = Yv[(size_t)s * 32 + lane];
        acc.x += v.x; acc.y += v.y; acc.z += v.z; acc.w += v.w;
    }

    float dv = g_dinv[d];
    float4 b = ((const float4*)bias)[lane];
    float4 o;
    o.x = fmaxf(fmaf(acc.x, dv, b.x), 0.f);
    o.y = fmaxf(fmaf(acc.y, dv, b.y), 0.f);
    o.z = fmaxf(fmaf(acc.z, dv, b.z), 0.f);
    o.w = fmaxf(fmaf(acc.w, dv, b.w), 0.f);
    ((float4*)H)[(size_t)d * 32 + lane] = o;
}

// ---------------- pooling: segmented partial sums over sorted batch ----------------
__global__ void k_pool(const float* __restrict__ H,
                       const int* __restrict__ batch) {
    const int CH = 512;
    int f = threadIdx.x;                       // 128 threads = feature index
    int n0 = blockIdx.x * CH;
    if (n0 >= NN) return;
    int n1 = n0 + CH; if (n1 > NN) n1 = NN;

    int cur = batch[n0];
    float acc = 0.f, c = 0.f;
    for (int n = n0; n < n1; n++) {
        int g = batch[n];
        if (g != cur) {
            atomicAdd(&g_pool[cur * C + f], acc);
            if (f == 0) atomicAdd(&g_gcnt[cur], c);
            acc = 0.f; c = 0.f; cur = g;
        }
        acc += H[(size_t)n * C + f];
        c += 1.f;
    }
    atomicAdd(&g_pool[cur * C + f], acc);
    if (f == 0) atomicAdd(&g_gcnt[cur], c);
}

// ---------------- final linear: out = (pool/cnt) @ Wlin + blin ----------------
__global__ void k_final(const float* __restrict__ Wlin,
                        const float* __restrict__ blin,
                        float* __restrict__ out) {
    int t = threadIdx.x;
    if (t >= NG * OUTC) return;
    int g = t / OUTC, o = t % OUTC;
    float inv = 1.f / fmaxf(g_gcnt[g], 1.f);
    float s = blin[o];
    #pragma unroll 8
    for (int k = 0; k < C; k++)
        s = fmaf(g_pool[g * C + k] * inv, Wlin[k * OUTC + o], s);
    out[t] = s;
}

// ---------------- launch ----------------
extern "C" void kernel_launch(void* const* d_in, const int* in_sizes, int n_in,
                              void* d_out, int out_size) {
    const float* x     = (const float*)d_in[0];
    const int*   ei    = (const int*)d_in[1];   // [2, E] int32 (JAX x32 default)
    const int*   batch = (const int*)d_in[2];   // [N] int32 (sorted)
    const float* W1    = (const float*)d_in[3];
    const float* b1    = (const float*)d_in[4];
    const float* W2    = (const float*)d_in[5];
    const float* b2    = (const float*)d_in[6];
    const float* Wlin  = (const float*)d_in[7];
    const float* blin  = (const float*)d_in[8];
    float* out = (float*)d_out;

    const int* src = ei;
    const int* dst = ei + EE;

    float *bufA, *bufB, *dinv;
    cudaGetSymbolAddress((void**)&bufA, g_bufA);
    cudaGetSymbolAddress((void**)&bufB, g_bufB);
    cudaGetSymbolAddress((void**)&dinv, g_dinv);

    // CSR build
    k_zero<<<256, 256>>>();
    k_hist<<<2048, 256>>>(dst);
    k_scan<<<1, 1024>>>();
    k_fill<<<2048, 256>>>(src, dst);

    const int gemm_blocks = (NN + 127) / 128;
    const int agg_blocks  = (NN * 32 + 255) / 256;

    // layer 1
    k_gemm<<<gemm_blocks, 256>>>(x, W1, bufA, dinv, NN);
    k_agg<<<agg_blocks, 256>>>(bufA, bufB, b1);
    // layer 2
    k_gemm<<<gemm_blocks, 256>>>(bufB, W2, bufA, dinv, NN);
    k_agg<<<agg_blocks, 256>>>(bufA, bufB, b2);

    // pooling + final linear
    k_pool<<<(NN + 511) / 512, 128>>>(bufB, batch);
    k_final<<<1, NG * OUTC>>>(Wlin, blin, out);
}

// round 3
// speedup vs baseline: 2.0346x; 2.0346x over previous
#include <cuda_runtime.h>
#include <cstdint>

#define NN 100000
#define EE 1600000
#define C  128
#define NG 64
#define OUTC 10
#define SCAN_BLOCKS ((NN + 255) / 256)   // 391

// ---------------- scratch (static __device__, no allocs) ----------------
__device__ float g_bufA[(size_t)NN * C];   // y = dinv * (x@W)
__device__ float g_bufB[(size_t)NN * C];   // h
__device__ float g_dinv[NN];
__device__ int   g_cnt[NN];
__device__ int   g_rowoff[NN + 1];
__device__ int   g_cursor[NN];
__device__ int   g_csr[EE];
__device__ int   g_bsum[512];
__device__ int   g_boff[512];
__device__ float g_pool[NG * C];
__device__ float g_gcnt[NG];

// ---------------- zero scratch ----------------
__global__ void k_zero() {
    int i = blockIdx.x * blockDim.x + threadIdx.x;
    int stride = gridDim.x * blockDim.x;
    for (int j = i; j < NN; j += stride) g_cnt[j] = 0;
    if (i < NG * C) g_pool[i] = 0.f;
    if (i < NG)     g_gcnt[i] = 0.f;
}

// ---------------- in-degree histogram over dst ----------------
__global__ void k_hist(const int* __restrict__ dst) {
    int i = blockIdx.x * blockDim.x + threadIdx.x;
    int stride = gridDim.x * blockDim.x;
    for (int e = i; e < EE; e += stride)
        atomicAdd(&g_cnt[dst[e]], 1);
}

// ---------------- parallel scan: pass 1 (per-block local excl scan + block sum) ----------------
__global__ void k_scan1() {
    __shared__ int wsum[8];
    int tid = threadIdx.x, lane = tid & 31, wid = tid >> 5;
    int i = blockIdx.x * 256 + tid;
    int v = (i < NN) ? g_cnt[i] : 0;
    int x = v;
    #pragma unroll
    for (int o = 1; o < 32; o <<= 1) {
        int t = __shfl_up_sync(0xffffffffu, x, o);
        if (lane >= o) x += t;
    }
    if (lane == 31) wsum[wid] = x;
    __syncthreads();
    if (wid == 0 && lane < 8) {
        int w = wsum[lane];
        int y = w;
        #pragma unroll
        for (int o = 1; o < 8; o <<= 1) {
            int t = __shfl_up_sync(0xffu, y, o);
            if (lane >= o) y += t;
        }
        wsum[lane] = y - w;   // exclusive
    }
    __syncthreads();
    int excl = x - v + wsum[wid];
    if (i < NN) g_rowoff[i] = excl;           // local exclusive, fixed up in pass 3
    if (tid == 255) g_bsum[blockIdx.x] = excl + v;
}

// ---------------- scan pass 2: scan block sums (single block, 512 thr) ----------------
__global__ void k_scan2() {
    __shared__ int wsum[16];
    int tid = threadIdx.x, lane = tid & 31, wid = tid >> 5;
    int v = (tid < SCAN_BLOCKS) ? g_bsum[tid] : 0;
    int x = v;
    #pragma unroll
    for (int o = 1; o < 32; o <<= 1) {
        int t = __shfl_up_sync(0xffffffffu, x, o);
        if (lane >= o) x += t;
    }
    if (lane == 31) wsum[wid] = x;
    __syncthreads();
    if (wid == 0 && lane < 16) {
        int w = wsum[lane];
        int y = w;
        #pragma unroll
        for (int o = 1; o < 16; o <<= 1) {
            int t = __shfl_up_sync(0xffffu, y, o);
            if (lane >= o) y += t;
        }
        wsum[lane] = y - w;
    }
    __syncthreads();
    int excl = x - v + wsum[wid];
    if (tid < SCAN_BLOCKS) g_boff[tid] = excl;
    if (tid == SCAN_BLOCKS - 1) g_rowoff[NN] = excl + v;
}

// ---------------- scan pass 3: add block offsets, init cursor + dinv ----------------
__global__ void k_scan3() {
    int i = blockIdx.x * 256 + threadIdx.x;
    if (i >= NN) return;
    int r = g_rowoff[i] + g_boff[blockIdx.x];
    g_rowoff[i] = r;
    g_cursor[i] = r;
    g_dinv[i] = rsqrtf((float)(g_cnt[i] + 1));
}

// ---------------- scatter edges into CSR buckets ----------------
__global__ void k_fill(const int* __restrict__ src,
                       const int* __restrict__ dst) {
    int i = blockIdx.x * blockDim.x + threadIdx.x;
    int stride = gridDim.x * blockDim.x;
    for (int e = i; e < EE; e += stride) {
        int d = dst[e];
        int pos = atomicAdd(&g_cursor[d], 1);
        g_csr[pos] = src[e];
    }
}

// ---------------- tf32 MMA GEMM: Y[m] = scale[m] * (A[m] @ W) ----------------
__device__ __forceinline__ uint32_t f2tf32(float x) {
    uint32_t r;
    asm("cvt.rna.tf32.f32 %0, %1;" : "=r"(r) : "f"(x));
    return r;
}

__global__ __launch_bounds__(256, 2)
void k_gemm_tf32(const float* __restrict__ A, const float* __restrict__ W,
                 float* __restrict__ Y, const float* __restrict__ scale, int M) {
    __shared__ float As[128][36];    // pad 36: MMA A-frag LDS conflict-free
    __shared__ float Bs[32][136];    // pad 136: MMA B-frag LDS conflict-free
    int tid = threadIdx.x;
    int wid = tid >> 5, lane = tid & 31;
    int warp_m = wid >> 2;           // 0..1 -> 64-row slab
    int warp_n = wid & 3;            // 0..3 -> 32-col slab
    int m0 = blockIdx.x * 128;
    int grp = lane >> 2, tig = lane & 3;

    float acc[4][4][4];
    #pragma unroll
    for (int mt = 0; mt < 4; mt++)
        #pragma unroll
        for (int nt = 0; nt < 4; nt++)
            #pragma unroll
            for (int r = 0; r < 4; r++) acc[mt][nt][r] = 0.f;

    for (int k0 = 0; k0 < C; k0 += 32) {
        // load A chunk: 128 x 32 floats
        #pragma unroll
        for (int i = 0; i < 4; i++) {
            int idx = i * 256 + tid;
            int row = idx >> 3;
            int c4 = (idx & 7) << 2;
            float4 v = make_float4(0.f, 0.f, 0.f, 0.f);
            if (m0 + row < M)
                v = *(const float4*)&A[(size_t)(m0 + row) * C + k0 + c4];
            *(float4*)&As[row][c4] = v;
        }
        // load B chunk: 32 x 128 floats
        #pragma unroll
        for (int i = 0; i < 4; i++) {
            int idx = i * 256 + tid;
            int row = idx >> 5;
            int c4 = (idx & 31) << 2;
            *(float4*)&Bs[row][c4] = *(const float4*)&W[(size_t)(k0 + row) * C + c4];
        }
        __syncthreads();

        #pragma unroll
        for (int kk = 0; kk < 4; kk++) {
            int kb = kk * 8;
            uint32_t af[4][4];
            #pragma unroll
            for (int mt = 0; mt < 4; mt++) {
                int r = warp_m * 64 + mt * 16 + grp;
                int c = kb + tig;
                af[mt][0] = f2tf32(As[r][c]);
                af[mt][1] = f2tf32(As[r + 8][c]);
                af[mt][2] = f2tf32(As[r][c + 4]);
                af[mt][3] = f2tf32(As[r + 8][c + 4]);
            }
            uint32_t bf[4][2];
            #pragma unroll
            for (int nt = 0; nt < 4; nt++) {
                int col = warp_n * 32 + nt * 8 + grp;
                int kr = kb + tig;
                bf[nt][0] = f2tf32(Bs[kr][col]);
                bf[nt][1] = f2tf32(Bs[kr + 4][col]);
            }
            #pragma unroll
            for (int mt = 0; mt < 4; mt++)
                #pragma unroll
                for (int nt = 0; nt < 4; nt++) {
                    asm volatile(
                        "mma.sync.aligned.m16n8k8.row.col.f32.tf32.tf32.f32 "
                        "{%0,%1,%2,%3}, {%4,%5,%6,%7}, {%8,%9}, {%0,%1,%2,%3};"
                        : "+f"(acc[mt][nt][0]), "+f"(acc[mt][nt][1]),
                          "+f"(acc[mt][nt][2]), "+f"(acc[mt][nt][3])
                        : "r"(af[mt][0]), "r"(af[mt][1]), "r"(af[mt][2]), "r"(af[mt][3]),
                          "r"(bf[nt][0]), "r"(bf[nt][1]));
                }
        }
        __syncthreads();
    }

    // epilogue: row scale + store
    #pragma unroll
    for (int mt = 0; mt < 4; mt++) {
        int r0 = m0 + warp_m * 64 + mt * 16 + grp;
        int r1 = r0 + 8;
        float s0 = (r0 < M) ? scale[r0] : 0.f;
        float s1 = (r1 < M) ? scale[r1] : 0.f;
        #pragma unroll
        for (int nt = 0; nt < 4; nt++) {
            int col = warp_n * 32 + nt * 8 + tig * 2;
            if (r0 < M) {
                float2 o = make_float2(acc[mt][nt][0] * s0, acc[mt][nt][1] * s0);
                *(float2*)&Y[(size_t)r0 * C + col] = o;
            }
            if (r1 < M) {
                float2 o = make_float2(acc[mt][nt][2] * s1, acc[mt][nt][3] * s1);
                *(float2*)&Y[(size_t)r1 * C + col] = o;
            }
        }
    }
}

// ---------------- aggregation: warp per dst node, pure gather ----------------
__global__ __launch_bounds__(256)
void k_agg(const float* __restrict__ Y, float* __restrict__ H,
           const float* __restrict__ bias) {
    int t = blockIdx.x * blockDim.x + threadIdx.x;
    int d = t >> 5;
    if (d >= NN) return;
    int lane = t & 31;
    const float4* Yv = (const float4*)Y;

    float4 acc = Yv[(size_t)d * 32 + lane];   // self loop term
    int e = g_rowoff[d], end = g_rowoff[d + 1];

    for (; e + 4 <= end; e += 4) {
        int s0 = g_csr[e], s1 = g_csr[e + 1], s2 = g_csr[e + 2], s3 = g_csr[e + 3];
        float4 v0 = Yv[(size_t)s0 * 32 + lane];
        float4 v1 = Yv[(size_t)s1 * 32 + lane];
        float4 v2 = Yv[(size_t)s2 * 32 + lane];
        float4 v3 = Yv[(size_t)s3 * 32 + lane];
        acc.x += (v0.x + v1.x) + (v2.x + v3.x);
        acc.y += (v0.y + v1.y) + (v2.y + v3.y);
        acc.z += (v0.z + v1.z) + (v2.z + v3.z);
        acc.w += (v0.w + v1.w) + (v2.w + v3.w);
    }
    for (; e < end; e++) {
        int s = g_csr[e];
        float4 v = Yv[(size_t)s * 32 + lane];
        acc.x += v.x; acc.y += v.y; acc.z += v.z; acc.w += v.w;
    }

    float dv = g_dinv[d];
    float4 b = ((const float4*)bias)[lane];
    float4 o;
    o.x = fmaxf(fmaf(acc.x, dv, b.x), 0.f);
    o.y = fmaxf(fmaf(acc.y, dv, b.y), 0.f);
    o.z = fmaxf(fmaf(acc.z, dv, b.z), 0.f);
    o.w = fmaxf(fmaf(acc.w, dv, b.w), 0.f);
    ((float4*)H)[(size_t)d * 32 + lane] = o;
}

// ---------------- pooling: segmented partial sums over sorted batch ----------------
__global__ void k_pool(const float* __restrict__ H,
                       const int* __restrict__ batch) {
    const int CH = 128;
    int f = threadIdx.x;                       // feature index
    int n0 = blockIdx.x * CH;
    if (n0 >= NN) return;
    int n1 = n0 + CH; if (n1 > NN) n1 = NN;

    int cur = batch[n0];
    float acc = 0.f, c = 0.f;
    for (int n = n0; n < n1; n++) {
        int g = batch[n];
        if (g != cur) {
            atomicAdd(&g_pool[cur * C + f], acc);
            if (f == 0) atomicAdd(&g_gcnt[cur], c);
            acc = 0.f; c = 0.f; cur = g;
        }
        acc += H[(size_t)n * C + f];
        c += 1.f;
    }
    atomicAdd(&g_pool[cur * C + f], acc);
    if (f == 0) atomicAdd(&g_gcnt[cur], c);
}

// ---------------- final linear: out = (pool/cnt) @ Wlin + blin ----------------
__global__ void k_final(const float* __restrict__ Wlin,
                        const float* __restrict__ blin,
                        float* __restrict__ out) {
    int t = threadIdx.x;
    if (t >= NG * OUTC) return;
    int g = t / OUTC, o = t % OUTC;
    float inv = 1.f / fmaxf(g_gcnt[g], 1.f);
    float s = blin[o];
    #pragma unroll 8
    for (int k = 0; k < C; k++)
        s = fmaf(g_pool[g * C + k] * inv, Wlin[k * OUTC + o], s);
    out[t] = s;
}

// ---------------- launch ----------------
extern "C" void kernel_launch(void* const* d_in, const int* in_sizes, int n_in,
                              void* d_out, int out_size) {
    const float* x     = (const float*)d_in[0];
    const int*   ei    = (const int*)d_in[1];   // [2, E] int32
    const int*   batch = (const int*)d_in[2];   // [N] int32 (sorted)
    const float* W1    = (const float*)d_in[3];
    const float* b1    = (const float*)d_in[4];
    const float* W2    = (const float*)d_in[5];
    const float* b2    = (const float*)d_in[6];
    const float* Wlin  = (const float*)d_in[7];
    const float* blin  = (const float*)d_in[8];
    float* out = (float*)d_out;

    const int* src = ei;
    const int* dst = ei + EE;

    float *bufA, *bufB, *dinv;
    cudaGetSymbolAddress((void**)&bufA, g_bufA);
    cudaGetSymbolAddress((void**)&bufB, g_bufB);
    cudaGetSymbolAddress((void**)&dinv, g_dinv);

    // CSR build
    k_zero<<<256, 256>>>();
    k_hist<<<2048, 256>>>(dst);
    k_scan1<<<SCAN_BLOCKS, 256>>>();
    k_scan2<<<1, 512>>>();
    k_scan3<<<SCAN_BLOCKS, 256>>>();
    k_fill<<<2048, 256>>>(src, dst);

    const int gemm_blocks = (NN + 127) / 128;
    const int agg_blocks  = (NN * 32 + 255) / 256;

    // layer 1
    k_gemm_tf32<<<gemm_blocks, 256>>>(x, W1, bufA, dinv, NN);
    k_agg<<<agg_blocks, 256>>>(bufA, bufB, b1);
    // layer 2
    k_gemm_tf32<<<gemm_blocks, 256>>>(bufB, W2, bufA, dinv, NN);
    k_agg<<<agg_blocks, 256>>>(bufA, bufB, b2);

    // pooling + final linear
    k_pool<<<(NN + 127) / 128, 128>>>(bufB, batch);
    k_final<<<1, NG * OUTC>>>(Wlin, blin, out);
}

// round 6
// speedup vs baseline: 2.4162x; 1.1876x over previous
#include <cuda_runtime.h>
#include <cuda_fp16.h>
#include <cstdint>

#define NN 100000
#define EE 1600000
#define C  128
#define NG 64
#define OUTC 10
#define SCAN_BLOCKS ((NN + 255) / 256)   // 391

// ---------------- scratch (static __device__, no allocs) ----------------
__device__ __half g_bufA[(size_t)NN * C];  // y = dinv * (x@W), fp16
__device__ __half g_bufB[(size_t)NN * C];  // h, fp16
__device__ float  g_dinv[NN];
__device__ int    g_cnt[NN];
__device__ int    g_rowoff[NN + 1];
__device__ int    g_cursor[NN];
__device__ int    g_csr[EE];
__device__ int    g_bsum[512];
__device__ int    g_boff[512];
__device__ float  g_pool[NG * C];
__device__ float  g_gcnt[NG];

// ---------------- zero scratch ----------------
__global__ void k_zero() {
    int i = blockIdx.x * blockDim.x + threadIdx.x;
    int stride = gridDim.x * blockDim.x;
    for (int j = i; j < NN; j += stride) g_cnt[j] = 0;
    if (i < NG * C) g_pool[i] = 0.f;
    if (i < NG)     g_gcnt[i] = 0.f;
}

// ---------------- in-degree histogram over dst ----------------
__global__ void k_hist(const int* __restrict__ dst) {
    int i = blockIdx.x * blockDim.x + threadIdx.x;
    int stride = gridDim.x * blockDim.x;
    for (int e = i; e < EE; e += stride)
        atomicAdd(&g_cnt[dst[e]], 1);
}

// ---------------- parallel scan pass 1 ----------------
__global__ void k_scan1() {
    __shared__ int wsum[8];
    int tid = threadIdx.x, lane = tid & 31, wid = tid >> 5;
    int i = blockIdx.x * 256 + tid;
    int v = (i < NN) ? g_cnt[i] : 0;
    int x = v;
    #pragma unroll
    for (int o = 1; o < 32; o <<= 1) {
        int t = __shfl_up_sync(0xffffffffu, x, o);
        if (lane >= o) x += t;
    }
    if (lane == 31) wsum[wid] = x;
    __syncthreads();
    if (wid == 0 && lane < 8) {
        int w = wsum[lane];
        int y = w;
        #pragma unroll
        for (int o = 1; o < 8; o <<= 1) {
            int t = __shfl_up_sync(0xffu, y, o);
            if (lane >= o) y += t;
        }
        wsum[lane] = y - w;
    }
    __syncthreads();
    int excl = x - v + wsum[wid];
    if (i < NN) g_rowoff[i] = excl;
    if (tid == 255) g_bsum[blockIdx.x] = excl + v;
}

// ---------------- scan pass 2 ----------------
__global__ void k_scan2() {
    __shared__ int wsum[16];
    int tid = threadIdx.x, lane = tid & 31, wid = tid >> 5;
    int v = (tid < SCAN_BLOCKS) ? g_bsum[tid] : 0;
    int x = v;
    #pragma unroll
    for (int o = 1; o < 32; o <<= 1) {
        int t = __shfl_up_sync(0xffffffffu, x, o);
        if (lane >= o) x += t;
    }
    if (lane == 31) wsum[wid] = x;
    __syncthreads();
    if (wid == 0 && lane < 16) {
        int w = wsum[lane];
        int y = w;
        #pragma unroll
        for (int o = 1; o < 16; o <<= 1) {
            int t = __shfl_up_sync(0xffffu, y, o);
            if (lane >= o) y += t;
        }
        wsum[lane] = y - w;
    }
    __syncthreads();
    int excl = x - v + wsum[wid];
    if (tid < SCAN_BLOCKS) g_boff[tid] = excl;
    if (tid == SCAN_BLOCKS - 1) g_rowoff[NN] = excl + v;
}

// ---------------- scan pass 3 ----------------
__global__ void k_scan3() {
    int i = blockIdx.x * 256 + threadIdx.x;
    if (i >= NN) return;
    int r = g_rowoff[i] + g_boff[blockIdx.x];
    g_rowoff[i] = r;
    g_cursor[i] = r;
    g_dinv[i] = rsqrtf((float)(g_cnt[i] + 1));
}

// ---------------- scatter edges into CSR buckets ----------------
__global__ void k_fill(const int* __restrict__ src,
                       const int* __restrict__ dst) {
    int i = blockIdx.x * blockDim.x + threadIdx.x;
    int stride = gridDim.x * blockDim.x;
    for (int e = i; e < EE; e += stride) {
        int d = dst[e];
        int pos = atomicAdd(&g_cursor[d], 1);
        g_csr[pos] = src[e];
    }
}

// ---------------- tf32 MMA GEMM: Yh[m] = half( scale[m] * (A[m] @ W) ) ----------------
__device__ __forceinline__ uint32_t f2tf32(float x) {
    uint32_t r;
    asm("cvt.rna.tf32.f32 %0, %1;" : "=r"(r) : "f"(x));
    return r;
}

__device__ __forceinline__ float4 load4(const float* p) { return *(const float4*)p; }
__device__ __forceinline__ float4 load4(const __half* p) {
    uint2 r = *(const uint2*)p;
    __half2 h01 = *reinterpret_cast<const __half2*>(&r.x);
    __half2 h23 = *reinterpret_cast<const __half2*>(&r.y);
    float2 f01 = __half22float2(h01);
    float2 f23 = __half22float2(h23);
    return make_float4(f01.x, f01.y, f23.x, f23.y);
}

template <typename TIn>
__global__ __launch_bounds__(256, 2)
void k_gemm_tf32(const TIn* __restrict__ A, const float* __restrict__ W,
                 __half* __restrict__ Y, const float* __restrict__ scale, int M) {
    __shared__ float As[128][36];
    __shared__ float Bs[32][136];
    int tid = threadIdx.x;
    int wid = tid >> 5, lane = tid & 31;
    int warp_m = wid >> 2;
    int warp_n = wid & 3;
    int m0 = blockIdx.x * 128;
    int grp = lane >> 2, tig = lane & 3;

    float acc[4][4][4];
    #pragma unroll
    for (int mt = 0; mt < 4; mt++)
        #pragma unroll
        for (int nt = 0; nt < 4; nt++)
            #pragma unroll
            for (int r = 0; r < 4; r++) acc[mt][nt][r] = 0.f;

    for (int k0 = 0; k0 < C; k0 += 32) {
        #pragma unroll
        for (int i = 0; i < 4; i++) {
            int idx = i * 256 + tid;
            int row = idx >> 3;
            int c4 = (idx & 7) << 2;
            float4 v = make_float4(0.f, 0.f, 0.f, 0.f);
            if (m0 + row < M)
                v = load4(&A[(size_t)(m0 + row) * C + k0 + c4]);
            *(float4*)&As[row][c4] = v;
        }
        #pragma unroll
        for (int i = 0; i < 4; i++) {
            int idx = i * 256 + tid;
            int row = idx >> 5;
            int c4 = (idx & 31) << 2;
            *(float4*)&Bs[row][c4] = *(const float4*)&W[(size_t)(k0 + row) * C + c4];
        }
        __syncthreads();

        #pragma unroll
        for (int kk = 0; kk < 4; kk++) {
            int kb = kk * 8;
            uint32_t af[4][4];
            #pragma unroll
            for (int mt = 0; mt < 4; mt++) {
                int r = warp_m * 64 + mt * 16 + grp;
                int c = kb + tig;
                af[mt][0] = f2tf32(As[r][c]);
                af[mt][1] = f2tf32(As[r + 8][c]);
                af[mt][2] = f2tf32(As[r][c + 4]);
                af[mt][3] = f2tf32(As[r + 8][c + 4]);
            }
            uint32_t bf[4][2];
            #pragma unroll
            for (int nt = 0; nt < 4; nt++) {
                int col = warp_n * 32 + nt * 8 + grp;
                int kr = kb + tig;
                bf[nt][0] = f2tf32(Bs[kr][col]);
                bf[nt][1] = f2tf32(Bs[kr + 4][col]);
            }
            #pragma unroll
            for (int mt = 0; mt < 4; mt++)
                #pragma unroll
                for (int nt = 0; nt < 4; nt++) {
                    asm volatile(
                        "mma.sync.aligned.m16n8k8.row.col.f32.tf32.tf32.f32 "
                        "{%0,%1,%2,%3}, {%4,%5,%6,%7}, {%8,%9}, {%0,%1,%2,%3};"
                        : "+f"(acc[mt][nt][0]), "+f"(acc[mt][nt][1]),
                          "+f"(acc[mt][nt][2]), "+f"(acc[mt][nt][3])
                        : "r"(af[mt][0]), "r"(af[mt][1]), "r"(af[mt][2]), "r"(af[mt][3]),
                          "r"(bf[nt][0]), "r"(bf[nt][1]));
                }
        }
        __syncthreads();
    }

    // epilogue: row scale + fp16 store
    #pragma unroll
    for (int mt = 0; mt < 4; mt++) {
        int r0 = m0 + warp_m * 64 + mt * 16 + grp;
        int r1 = r0 + 8;
        float s0 = (r0 < M) ? scale[r0] : 0.f;
        float s1 = (r1 < M) ? scale[r1] : 0.f;
        #pragma unroll
        for (int nt = 0; nt < 4; nt++) {
            int col = warp_n * 32 + nt * 8 + tig * 2;
            if (r0 < M) {
                __half2 h = __floats2half2_rn(acc[mt][nt][0] * s0, acc[mt][nt][1] * s0);
                *(__half2*)&Y[(size_t)r0 * C + col] = h;
            }
            if (r1 < M) {
                __half2 h = __floats2half2_rn(acc[mt][nt][2] * s1, acc[mt][nt][3] * s1);
                *(__half2*)&Y[(size_t)r1 * C + col] = h;
            }
        }
    }
}

// ---------------- aggregation: warp per dst node, fp16 gather / fp32 accum ----------------
__device__ __forceinline__ void acc_add(float4& a, uint2 r) {
    __half2 h01 = *reinterpret_cast<const __half2*>(&r.x);
    __half2 h23 = *reinterpret_cast<const __half2*>(&r.y);
    float2 f01 = __half22float2(h01);
    float2 f23 = __half22float2(h23);
    a.x += f01.x; a.y += f01.y; a.z += f23.x; a.w += f23.y;
}

__global__ __launch_bounds__(256)
void k_agg(const __half* __restrict__ Y, __half* __restrict__ H,
           const float* __restrict__ bias) {
    int t = blockIdx.x * blockDim.x + threadIdx.x;
    int d = t >> 5;
    if (d >= NN) return;
    int lane = t & 31;
    const uint2* Yv = (const uint2*)Y;   // 32 x 8B chunks per 128-feature row

    float4 acc = make_float4(0.f, 0.f, 0.f, 0.f);
    acc_add(acc, Yv[(size_t)d * 32 + lane]);   // self loop
    int e = g_rowoff[d], end = g_rowoff[d + 1];

    for (; e + 4 <= end; e += 4) {
        int s0 = g_csr[e], s1 = g_csr[e + 1], s2 = g_csr[e + 2], s3 = g_csr[e + 3];
        uint2 v0 = Yv[(size_t)s0 * 32 + lane];
        uint2 v1 = Yv[(size_t)s1 * 32 + lane];
        uint2 v2 = Yv[(size_t)s2 * 32 + lane];
        uint2 v3 = Yv[(size_t)s3 * 32 + lane];
        acc_add(acc, v0); acc_add(acc, v1); acc_add(acc, v2); acc_add(acc, v3);
    }
    for (; e < end; e++) {
        acc_add(acc, Yv[(size_t)g_csr[e] * 32 + lane]);
    }

    float dv = g_dinv[d];
    float4 b = ((const float4*)bias)[lane];
    float o0 = fmaxf(fmaf(acc.x, dv, b.x), 0.f);
    float o1 = fmaxf(fmaf(acc.y, dv, b.y), 0.f);
    float o2 = fmaxf(fmaf(acc.z, dv, b.z), 0.f);
    float o3 = fmaxf(fmaf(acc.w, dv, b.w), 0.f);
    uint2 out;
    __half2 h01 = __floats2half2_rn(o0, o1);
    __half2 h23 = __floats2half2_rn(o2, o3);
    out.x = *reinterpret_cast<uint32_t*>(&h01);
    out.y = *reinterpret_cast<uint32_t*>(&h23);
    ((uint2*)H)[(size_t)d * 32 + lane] = out;
}

// ---------------- pooling: segmented partial sums over sorted batch ----------------
__global__ void k_pool(const __half* __restrict__ H,
                       const int* __restrict__ batch) {
    const int CH = 128;
    int f = threadIdx.x;
    int n0 = blockIdx.x * CH;
    if (n0 >= NN) return;
    int n1 = n0 + CH; if (n1 > NN) n1 = NN;

    int cur = batch[n0];
    float acc = 0.f, c = 0.f;
    for (int n = n0; n < n1; n++) {
        int g = batch[n];
        if (g != cur) {
            atomicAdd(&g_pool[cur * C + f], acc);
            if (f == 0) atomicAdd(&g_gcnt[cur], c);
            acc = 0.f; c = 0.f; cur = g;
        }
        acc += __half2float(H[(size_t)n * C + f]);
        c += 1.f;
    }
    atomicAdd(&g_pool[cur * C + f], acc);
    if (f == 0) atomicAdd(&g_gcnt[cur], c);
}

// ---------------- final linear ----------------
__global__ void k_final(const float* __restrict__ Wlin,
                        const float* __restrict__ blin,
                        float* __restrict__ out) {
    int t = threadIdx.x;
    if (t >= NG * OUTC) return;
    int g = t / OUTC, o = t % OUTC;
    float inv = 1.f / fmaxf(g_gcnt[g], 1.f);
    float s = blin[o];
    #pragma unroll 8
    for (int k = 0; k < C; k++)
        s = fmaf(g_pool[g * C + k] * inv, Wlin[k * OUTC + o], s);
    out[t] = s;
}

// ---------------- launch ----------------
extern "C" void kernel_launch(void* const* d_in, const int* in_sizes, int n_in,
                              void* d_out, int out_size) {
    const float* x     = (const float*)d_in[0];
    const int*   ei    = (const int*)d_in[1];
    const int*   batch = (const int*)d_in[2];
    const float* W1    = (const float*)d_in[3];
    const float* b1    = (const float*)d_in[4];
    const float* W2    = (const float*)d_in[5];
    const float* b2    = (const float*)d_in[6];
    const float* Wlin  = (const float*)d_in[7];
    const float* blin  = (const float*)d_in[8];
    float* out = (float*)d_out;

    const int* src = ei;
    const int* dst = ei + EE;

    __half *bufA, *bufB;
    float *dinv;
    cudaGetSymbolAddress((void**)&bufA, g_bufA);
    cudaGetSymbolAddress((void**)&bufB, g_bufB);
    cudaGetSymbolAddress((void**)&dinv, g_dinv);

    // CSR build
    k_zero<<<256, 256>>>();
    k_hist<<<2048, 256>>>(dst);
    k_scan1<<<SCAN_BLOCKS, 256>>>();
    k_scan2<<<1, 512>>>();
    k_scan3<<<SCAN_BLOCKS, 256>>>();
    k_fill<<<2048, 256>>>(src, dst);

    const int gemm_blocks = (NN + 127) / 128;
    const int agg_blocks  = (NN * 32 + 255) / 256;

    // layer 1
    k_gemm_tf32<float><<<gemm_blocks, 256>>>(x, W1, bufA, dinv, NN);
    k_agg<<<agg_blocks, 256>>>(bufA, bufB, b1);
    // layer 2
    k_gemm_tf32<__half><<<gemm_blocks, 256>>>(bufB, W2, bufA, dinv, NN);
    k_agg<<<agg_blocks, 256>>>(bufA, bufB, b2);

    // pooling + final linear
    k_pool<<<(NN + 127) / 128, 128>>>(bufB, batch);
    k_final<<<1, NG * OUTC>>>(Wlin, blin, out);
}

// round 9
// speedup vs baseline: 2.5402x; 1.0513x over previous
#include <cuda_runtime.h>
#include <cuda_fp16.h>
#include <cstdint>

#define NN 100000
#define EE 1600000
#define C  128
#define NG 64
#define OUTC 10
#define SCAN_BLOCKS ((NN + 255) / 256)   // 391

// ---------------- scratch (static __device__, no allocs) ----------------
__device__ __half g_bufA[(size_t)NN * C];  // y = dinv * (x@W), fp16
__device__ __half g_bufB[(size_t)NN * C];  // h, fp16
__device__ float  g_dinv[NN];
__device__ int    g_cnt[NN];
__device__ int    g_rowoff[NN + 1];
__device__ int    g_cursor[NN];
__device__ int    g_csr[EE];
__device__ int    g_bsum[512];
__device__ int    g_boff[512];
__device__ float  g_pool[NG * C];
__device__ float  g_gcnt[NG];

// ---------------- zero scratch ----------------
__global__ void k_zero() {
    int i = blockIdx.x * blockDim.x + threadIdx.x;
    int stride = gridDim.x * blockDim.x;
    for (int j = i; j < NN; j += stride) g_cnt[j] = 0;
    if (i < NG * C) g_pool[i] = 0.f;
    if (i < NG)     g_gcnt[i] = 0.f;
}

// ---------------- in-degree histogram over dst (int4 loads) ----------------
__global__ void k_hist(const int4* __restrict__ dst4) {
    int i = blockIdx.x * blockDim.x + threadIdx.x;
    int stride = gridDim.x * blockDim.x;
    for (int e = i; e < EE / 4; e += stride) {
        int4 v = dst4[e];
        atomicAdd(&g_cnt[v.x], 1);
        atomicAdd(&g_cnt[v.y], 1);
        atomicAdd(&g_cnt[v.z], 1);
        atomicAdd(&g_cnt[v.w], 1);
    }
}

// ---------------- parallel scan pass 1 ----------------
__global__ void k_scan1() {
    __shared__ int wsum[8];
    int tid = threadIdx.x, lane = tid & 31, wid = tid >> 5;
    int i = blockIdx.x * 256 + tid;
    int v = (i < NN) ? g_cnt[i] : 0;
    int x = v;
    #pragma unroll
    for (int o = 1; o < 32; o <<= 1) {
        int t = __shfl_up_sync(0xffffffffu, x, o);
        if (lane >= o) x += t;
    }
    if (lane == 31) wsum[wid] = x;
    __syncthreads();
    if (wid == 0 && lane < 8) {
        int w = wsum[lane];
        int y = w;
        #pragma unroll
        for (int o = 1; o < 8; o <<= 1) {
            int t = __shfl_up_sync(0xffu, y, o);
            if (lane >= o) y += t;
        }
        wsum[lane] = y - w;
    }
    __syncthreads();
    int excl = x - v + wsum[wid];
    if (i < NN) g_rowoff[i] = excl;
    if (tid == 255) g_bsum[blockIdx.x] = excl + v;
}

// ---------------- scan pass 2 ----------------
__global__ void k_scan2() {
    __shared__ int wsum[16];
    int tid = threadIdx.x, lane = tid & 31, wid = tid >> 5;
    int v = (tid < SCAN_BLOCKS) ? g_bsum[tid] : 0;
    int x = v;
    #pragma unroll
    for (int o = 1; o < 32; o <<= 1) {
        int t = __shfl_up_sync(0xffffffffu, x, o);
        if (lane >= o) x += t;
    }
    if (lane == 31) wsum[wid] = x;
    __syncthreads();
    if (wid == 0 && lane < 16) {
        int w = wsum[lane];
        int y = w;
        #pragma unroll
        for (int o = 1; o < 16; o <<= 1) {
            int t = __shfl_up_sync(0xffffu, y, o);
            if (lane >= o) y += t;
        }
        wsum[lane] = y - w;
    }
    __syncthreads();
    int excl = x - v + wsum[wid];
    if (tid < SCAN_BLOCKS) g_boff[tid] = excl;
    if (tid == SCAN_BLOCKS - 1) g_rowoff[NN] = excl + v;
}

// ---------------- scan pass 3 ----------------
__global__ void k_scan3() {
    int i = blockIdx.x * 256 + threadIdx.x;
    if (i >= NN) return;
    int r = g_rowoff[i] + g_boff[blockIdx.x];
    g_rowoff[i] = r;
    g_cursor[i] = r;
    g_dinv[i] = rsqrtf((float)(g_cnt[i] + 1));
}

// ---------------- scatter edges into CSR buckets (int4 loads) ----------------
__global__ void k_fill(const int4* __restrict__ src4,
                       const int4* __restrict__ dst4) {
    int i = blockIdx.x * blockDim.x + threadIdx.x;
    int stride = gridDim.x * blockDim.x;
    for (int e = i; e < EE / 4; e += stride) {
        int4 d = dst4[e];
        int4 s = src4[e];
        g_csr[atomicAdd(&g_cursor[d.x], 1)] = s.x;
        g_csr[atomicAdd(&g_cursor[d.y], 1)] = s.y;
        g_csr[atomicAdd(&g_cursor[d.z], 1)] = s.z;
        g_csr[atomicAdd(&g_cursor[d.w], 1)] = s.w;
    }
}

// ---------------- tf32 MMA GEMM: Yh[m] = half( scale[m] * (A[m] @ W) ) ----------------
__device__ __forceinline__ uint32_t f2tf32(float x) {
    uint32_t r;
    asm("cvt.rna.tf32.f32 %0, %1;" : "=r"(r) : "f"(x));
    return r;
}

__device__ __forceinline__ float4 load4(const float* p) { return *(const float4*)p; }
__device__ __forceinline__ float4 load4(const __half* p) {
    uint2 r = *(const uint2*)p;
    __half2 h01 = *reinterpret_cast<const __half2*>(&r.x);
    __half2 h23 = *reinterpret_cast<const __half2*>(&r.y);
    float2 f01 = __half22float2(h01);
    float2 f23 = __half22float2(h23);
    return make_float4(f01.x, f01.y, f23.x, f23.y);
}

template <typename TIn>
__global__ __launch_bounds__(256, 2)
void k_gemm_tf32(const TIn* __restrict__ A, const float* __restrict__ W,
                 __half* __restrict__ Y, const float* __restrict__ scale, int M) {
    __shared__ float As[128][36];
    __shared__ float Bs[32][136];
    int tid = threadIdx.x;
    int wid = tid >> 5, lane = tid & 31;
    int warp_m = wid >> 2;
    int warp_n = wid & 3;
    int m0 = blockIdx.x * 128;
    int grp = lane >> 2, tig = lane & 3;

    float acc[4][4][4];
    #pragma unroll
    for (int mt = 0; mt < 4; mt++)
        #pragma unroll
        for (int nt = 0; nt < 4; nt++)
            #pragma unroll
            for (int r = 0; r < 4; r++) acc[mt][nt][r] = 0.f;

    for (int k0 = 0; k0 < C; k0 += 32) {
        #pragma unroll
        for (int i = 0; i < 4; i++) {
            int idx = i * 256 + tid;
            int row = idx >> 3;
            int c4 = (idx & 7) << 2;
            float4 v = make_float4(0.f, 0.f, 0.f, 0.f);
            if (m0 + row < M)
                v = load4(&A[(size_t)(m0 + row) * C + k0 + c4]);
            *(float4*)&As[row][c4] = v;
        }
        #pragma unroll
        for (int i = 0; i < 4; i++) {
            int idx = i * 256 + tid;
            int row = idx >> 5;
            int c4 = (idx & 31) << 2;
            *(float4*)&Bs[row][c4] = *(const float4*)&W[(size_t)(k0 + row) * C + c4];
        }
        __syncthreads();

        #pragma unroll
        for (int kk = 0; kk < 4; kk++) {
            int kb = kk * 8;
            uint32_t af[4][4];
            #pragma unroll
            for (int mt = 0; mt < 4; mt++) {
                int r = warp_m * 64 + mt * 16 + grp;
                int c = kb + tig;
                af[mt][0] = f2tf32(As[r][c]);
                af[mt][1] = f2tf32(As[r + 8][c]);
                af[mt][2] = f2tf32(As[r][c + 4]);
                af[mt][3] = f2tf32(As[r + 8][c + 4]);
            }
            uint32_t bf[4][2];
            #pragma unroll
            for (int nt = 0; nt < 4; nt++) {
                int col = warp_n * 32 + nt * 8 + grp;
                int kr = kb + tig;
                bf[nt][0] = f2tf32(Bs[kr][col]);
                bf[nt][1] = f2tf32(Bs[kr + 4][col]);
            }
            #pragma unroll
            for (int mt = 0; mt < 4; mt++)
                #pragma unroll
                for (int nt = 0; nt < 4; nt++) {
                    asm volatile(
                        "mma.sync.aligned.m16n8k8.row.col.f32.tf32.tf32.f32 "
                        "{%0,%1,%2,%3}, {%4,%5,%6,%7}, {%8,%9}, {%0,%1,%2,%3};"
                        : "+f"(acc[mt][nt][0]), "+f"(acc[mt][nt][1]),
                          "+f"(acc[mt][nt][2]), "+f"(acc[mt][nt][3])
                        : "r"(af[mt][0]), "r"(af[mt][1]), "r"(af[mt][2]), "r"(af[mt][3]),
                          "r"(bf[nt][0]), "r"(bf[nt][1]));
                }
        }
        __syncthreads();
    }

    // epilogue: row scale + fp16 store
    #pragma unroll
    for (int mt = 0; mt < 4; mt++) {
        int r0 = m0 + warp_m * 64 + mt * 16 + grp;
        int r1 = r0 + 8;
        float s0 = (r0 < M) ? scale[r0] : 0.f;
        float s1 = (r1 < M) ? scale[r1] : 0.f;
        #pragma unroll
        for (int nt = 0; nt < 4; nt++) {
            int col = warp_n * 32 + nt * 8 + tig * 2;
            if (r0 < M) {
                __half2 h = __floats2half2_rn(acc[mt][nt][0] * s0, acc[mt][nt][1] * s0);
                *(__half2*)&Y[(size_t)r0 * C + col] = h;
            }
            if (r1 < M) {
                __half2 h = __floats2half2_rn(acc[mt][nt][2] * s1, acc[mt][nt][3] * s1);
                *(__half2*)&Y[(size_t)r1 * C + col] = h;
            }
        }
    }
}

// ---------------- aggregation: HALF-warp per dst node, uint4 (16B) fp16 gather ----------------
__device__ __forceinline__ void add8(float* a, uint4 v) {
    __half2 h0 = *reinterpret_cast<const __half2*>(&v.x);
    __half2 h1 = *reinterpret_cast<const __half2*>(&v.y);
    __half2 h2 = *reinterpret_cast<const __half2*>(&v.z);
    __half2 h3 = *reinterpret_cast<const __half2*>(&v.w);
    float2 f0 = __half22float2(h0), f1 = __half22float2(h1);
    float2 f2 = __half22float2(h2), f3 = __half22float2(h3);
    a[0] += f0.x; a[1] += f0.y; a[2] += f1.x; a[3] += f1.y;
    a[4] += f2.x; a[5] += f2.y; a[6] += f3.x; a[7] += f3.y;
}

__global__ __launch_bounds__(256)
void k_agg(const __half* __restrict__ Y, __half* __restrict__ H,
           const float* __restrict__ bias) {
    int t = blockIdx.x * blockDim.x + threadIdx.x;
    int d = t >> 4;                 // 16 lanes per node
    if (d >= NN) return;
    int lane = t & 15;              // lane covers features [lane*8, lane*8+8)
    const uint4* Yv = (const uint4*)Y;   // 16 uint4 chunks per 128-feature row

    float acc[8] = {0.f, 0.f, 0.f, 0.f, 0.f, 0.f, 0.f, 0.f};
    add8(acc, Yv[(size_t)d * 16 + lane]);    // self loop
    int e = g_rowoff[d], end = g_rowoff[d + 1];

    for (; e + 4 <= end; e += 4) {
        int s0 = g_csr[e], s1 = g_csr[e + 1], s2 = g_csr[e + 2], s3 = g_csr[e + 3];
        uint4 v0 = Yv[(size_t)s0 * 16 + lane];
        uint4 v1 = Yv[(size_t)s1 * 16 + lane];
        uint4 v2 = Yv[(size_t)s2 * 16 + lane];
        uint4 v3 = Yv[(size_t)s3 * 16 + lane];
        add8(acc, v0); add8(acc, v1); add8(acc, v2); add8(acc, v3);
    }
    for (; e < end; e++) {
        add8(acc, Yv[(size_t)g_csr[e] * 16 + lane]);
    }

    float dv = g_dinv[d];
    float4 b0 = ((const float4*)bias)[lane * 2];
    float4 b1 = ((const float4*)bias)[lane * 2 + 1];
    float o[8];
    o[0] = fmaxf(fmaf(acc[0], dv, b0.x), 0.f);
    o[1] = fmaxf(fmaf(acc[1], dv, b0.y), 0.f);
    o[2] = fmaxf(fmaf(acc[2], dv, b0.z), 0.f);
    o[3] = fmaxf(fmaf(acc[3], dv, b0.w), 0.f);
    o[4] = fmaxf(fmaf(acc[4], dv, b1.x), 0.f);
    o[5] = fmaxf(fmaf(acc[5], dv, b1.y), 0.f);
    o[6] = fmaxf(fmaf(acc[6], dv, b1.z), 0.f);
    o[7] = fmaxf(fmaf(acc[7], dv, b1.w), 0.f);
    __half2 p0 = __floats2half2_rn(o[0], o[1]);
    __half2 p1 = __floats2half2_rn(o[2], o[3]);
    __half2 p2 = __floats2half2_rn(o[4], o[5]);
    __half2 p3 = __floats2half2_rn(o[6], o[7]);
    uint4 outv;
    outv.x = *reinterpret_cast<uint32_t*>(&p0);
    outv.y = *reinterpret_cast<uint32_t*>(&p1);
    outv.z = *reinterpret_cast<uint32_t*>(&p2);
    outv.w = *reinterpret_cast<uint32_t*>(&p3);
    ((uint4*)H)[(size_t)d * 16 + lane] = outv;
}

// ---------------- pooling: segmented partial sums over sorted batch ----------------
__global__ void k_pool(const __half* __restrict__ H,
                       const int* __restrict__ batch) {
    const int CH = 128;
    int f = threadIdx.x;
    int n0 = blockIdx.x * CH;
    if (n0 >= NN) return;
    int n1 = n0 + CH; if (n1 > NN) n1 = NN;

    int cur = batch[n0];
    float acc = 0.f, c = 0.f;
    for (int n = n0; n < n1; n++) {
        int g = batch[n];
        if (g != cur) {
            atomicAdd(&g_pool[cur * C + f], acc);
            if (f == 0) atomicAdd(&g_gcnt[cur], c);
            acc = 0.f; c = 0.f; cur = g;
        }
        acc += __half2float(H[(size_t)n * C + f]);
        c += 1.f;
    }
    atomicAdd(&g_pool[cur * C + f], acc);
    if (f == 0) atomicAdd(&g_gcnt[cur], c);
}

// ---------------- final linear ----------------
__global__ void k_final(const float* __restrict__ Wlin,
                        const float* __restrict__ blin,
                        float* __restrict__ out) {
    int t = threadIdx.x;
    if (t >= NG * OUTC) return;
    int g = t / OUTC, o = t % OUTC;
    float inv = 1.f / fmaxf(g_gcnt[g], 1.f);
    float s = blin[o];
    #pragma unroll 8
    for (int k = 0; k < C; k++)
        s = fmaf(g_pool[g * C + k] * inv, Wlin[k * OUTC + o], s);
    out[t] = s;
}

// ---------------- launch ----------------
extern "C" void kernel_launch(void* const* d_in, const int* in_sizes, int n_in,
                              void* d_out, int out_size) {
    const float* x     = (const float*)d_in[0];
    const int*   ei    = (const int*)d_in[1];
    const int*   batch = (const int*)d_in[2];
    const float* W1    = (const float*)d_in[3];
    const float* b1    = (const float*)d_in[4];
    const float* W2    = (const float*)d_in[5];
    const float* b2    = (const float*)d_in[6];
    const float* Wlin  = (const float*)d_in[7];
    const float* blin  = (const float*)d_in[8];
    float* out = (float*)d_out;

    const int* src = ei;
    const int* dst = ei + EE;

    __half *bufA, *bufB;
    float *dinv;
    cudaGetSymbolAddress((void**)&bufA, g_bufA);
    cudaGetSymbolAddress((void**)&bufB, g_bufB);
    cudaGetSymbolAddress((void**)&dinv, g_dinv);

    // CSR build
    k_zero<<<256, 256>>>();
    k_hist<<<2048, 256>>>((const int4*)dst);
    k_scan1<<<SCAN_BLOCKS, 256>>>();
    k_scan2<<<1, 512>>>();
    k_scan3<<<SCAN_BLOCKS, 256>>>();
    k_fill<<<2048, 256>>>((const int4*)src, (const int4*)dst);

    const int gemm_blocks = (NN + 127) / 128;
    const int agg_blocks  = (NN * 16 + 255) / 256;

    // layer 1
    k_gemm_tf32<float><<<gemm_blocks, 256>>>(x, W1, bufA, dinv, NN);
    k_agg<<<agg_blocks, 256>>>(bufA, bufB, b1);
    // layer 2
    k_gemm_tf32<__half><<<gemm_blocks, 256>>>(bufB, W2, bufA, dinv, NN);
    k_agg<<<agg_blocks, 256>>>(bufA, bufB, b2);

    // pooling + final linear
    k_pool<<<(NN + 127) / 128, 128>>>(bufB, batch);
    k_final<<<1, NG * OUTC>>>(Wlin, blin, out);
}

// round 10
// speedup vs baseline: 2.5812x; 1.0162x over previous
#include <cuda_runtime.h>
#include <cuda_fp16.h>
#include <cstdint>

#define NN 100000
#define EE 1600000
#define C  128
#define NG 64
#define OUTC 10
#define SCAN_BLOCKS ((NN + 255) / 256)   // 391

// ---------------- scratch (static __device__, no allocs) ----------------
__device__ __half g_bufA[(size_t)NN * C];  // y = dinv * (x@W), fp16
__device__ __half g_bufB[(size_t)NN * C];  // h, fp16
__device__ float  g_dinv[NN];
__device__ int    g_cnt[NN];
__device__ int    g_rowoff[NN + 1];
__device__ int    g_cursor[NN];
__device__ int    g_csr[EE];
__device__ int    g_bsum[512];
__device__ int    g_boff[512];
__device__ float  g_pool[NG * C];
__device__ float  g_gcnt[NG];

// ---------------- zero scratch ----------------
__global__ void k_zero() {
    int i = blockIdx.x * blockDim.x + threadIdx.x;
    int stride = gridDim.x * blockDim.x;
    for (int j = i; j < NN; j += stride) g_cnt[j] = 0;
    if (i < NG * C) g_pool[i] = 0.f;
    if (i < NG)     g_gcnt[i] = 0.f;
}

// ---------------- in-degree histogram over dst (int4 loads) ----------------
__global__ void k_hist(const int4* __restrict__ dst4) {
    int i = blockIdx.x * blockDim.x + threadIdx.x;
    int stride = gridDim.x * blockDim.x;
    for (int e = i; e < EE / 4; e += stride) {
        int4 v = dst4[e];
        atomicAdd(&g_cnt[v.x], 1);
        atomicAdd(&g_cnt[v.y], 1);
        atomicAdd(&g_cnt[v.z], 1);
        atomicAdd(&g_cnt[v.w], 1);
    }
}

// ---------------- parallel scan pass 1 ----------------
__global__ void k_scan1() {
    __shared__ int wsum[8];
    int tid = threadIdx.x, lane = tid & 31, wid = tid >> 5;
    int i = blockIdx.x * 256 + tid;
    int v = (i < NN) ? g_cnt[i] : 0;
    int x = v;
    #pragma unroll
    for (int o = 1; o < 32; o <<= 1) {
        int t = __shfl_up_sync(0xffffffffu, x, o);
        if (lane >= o) x += t;
    }
    if (lane == 31) wsum[wid] = x;
    __syncthreads();
    if (wid == 0 && lane < 8) {
        int w = wsum[lane];
        int y = w;
        #pragma unroll
        for (int o = 1; o < 8; o <<= 1) {
            int t = __shfl_up_sync(0xffu, y, o);
            if (lane >= o) y += t;
        }
        wsum[lane] = y - w;
    }
    __syncthreads();
    int excl = x - v + wsum[wid];
    if (i < NN) g_rowoff[i] = excl;
    if (tid == 255) g_bsum[blockIdx.x] = excl + v;
}

// ---------------- scan pass 2 ----------------
__global__ void k_scan2() {
    __shared__ int wsum[16];
    int tid = threadIdx.x, lane = tid & 31, wid = tid >> 5;
    int v = (tid < SCAN_BLOCKS) ? g_bsum[tid] : 0;
    int x = v;
    #pragma unroll
    for (int o = 1; o < 32; o <<= 1) {
        int t = __shfl_up_sync(0xffffffffu, x, o);
        if (lane >= o) x += t;
    }
    if (lane == 31) wsum[wid] = x;
    __syncthreads();
    if (wid == 0 && lane < 16) {
        int w = wsum[lane];
        int y = w;
        #pragma unroll
        for (int o = 1; o < 16; o <<= 1) {
            int t = __shfl_up_sync(0xffffu, y, o);
            if (lane >= o) y += t;
        }
        wsum[lane] = y - w;
    }
    __syncthreads();
    int excl = x - v + wsum[wid];
    if (tid < SCAN_BLOCKS) g_boff[tid] = excl;
    if (tid == SCAN_BLOCKS - 1) g_rowoff[NN] = excl + v;
}

// ---------------- scan pass 3 ----------------
__global__ void k_scan3() {
    int i = blockIdx.x * 256 + threadIdx.x;
    if (i >= NN) return;
    int r = g_rowoff[i] + g_boff[blockIdx.x];
    g_rowoff[i] = r;
    g_cursor[i] = r;
    g_dinv[i] = rsqrtf((float)(g_cnt[i] + 1));
}

// ---------------- scatter edges into CSR buckets (int4 loads) ----------------
__global__ void k_fill(const int4* __restrict__ src4,
                       const int4* __restrict__ dst4) {
    int i = blockIdx.x * blockDim.x + threadIdx.x;
    int stride = gridDim.x * blockDim.x;
    for (int e = i; e < EE / 4; e += stride) {
        int4 d = dst4[e];
        int4 s = src4[e];
        g_csr[atomicAdd(&g_cursor[d.x], 1)] = s.x;
        g_csr[atomicAdd(&g_cursor[d.y], 1)] = s.y;
        g_csr[atomicAdd(&g_cursor[d.z], 1)] = s.z;
        g_csr[atomicAdd(&g_cursor[d.w], 1)] = s.w;
    }
}

// ---------------- tf32 MMA GEMM: Yh[m] = half( scale[m] * (A[m] @ W) ) ----------------
__device__ __forceinline__ uint32_t f2tf32(float x) {
    uint32_t r;
    asm("cvt.rna.tf32.f32 %0, %1;" : "=r"(r) : "f"(x));
    return r;
}

__device__ __forceinline__ float4 load4(const float* p) { return *(const float4*)p; }
__device__ __forceinline__ float4 load4(const __half* p) {
    uint2 r = *(const uint2*)p;
    __half2 h01 = *reinterpret_cast<const __half2*>(&r.x);
    __half2 h23 = *reinterpret_cast<const __half2*>(&r.y);
    float2 f01 = __half22float2(h01);
    float2 f23 = __half22float2(h23);
    return make_float4(f01.x, f01.y, f23.x, f23.y);
}

template <typename TIn>
__global__ __launch_bounds__(256, 2)
void k_gemm_tf32(const TIn* __restrict__ A, const float* __restrict__ W,
                 __half* __restrict__ Y, const float* __restrict__ scale, int M) {
    __shared__ float As[128][36];
    __shared__ float Bs[32][136];
    int tid = threadIdx.x;
    int wid = tid >> 5, lane = tid & 31;
    int warp_m = wid >> 2;
    int warp_n = wid & 3;
    int m0 = blockIdx.x * 128;
    int grp = lane >> 2, tig = lane & 3;

    float acc[4][4][4];
    #pragma unroll
    for (int mt = 0; mt < 4; mt++)
        #pragma unroll
        for (int nt = 0; nt < 4; nt++)
            #pragma unroll
            for (int r = 0; r < 4; r++) acc[mt][nt][r] = 0.f;

    for (int k0 = 0; k0 < C; k0 += 32) {
        #pragma unroll
        for (int i = 0; i < 4; i++) {
            int idx = i * 256 + tid;
            int row = idx >> 3;
            int c4 = (idx & 7) << 2;
            float4 v = make_float4(0.f, 0.f, 0.f, 0.f);
            if (m0 + row < M)
                v = load4(&A[(size_t)(m0 + row) * C + k0 + c4]);
            *(float4*)&As[row][c4] = v;
        }
        #pragma unroll
        for (int i = 0; i < 4; i++) {
            int idx = i * 256 + tid;
            int row = idx >> 5;
            int c4 = (idx & 31) << 2;
            *(float4*)&Bs[row][c4] = *(const float4*)&W[(size_t)(k0 + row) * C + c4];
        }
        __syncthreads();

        #pragma unroll
        for (int kk = 0; kk < 4; kk++) {
            int kb = kk * 8;
            uint32_t af[4][4];
            #pragma unroll
            for (int mt = 0; mt < 4; mt++) {
                int r = warp_m * 64 + mt * 16 + grp;
                int c = kb + tig;
                af[mt][0] = f2tf32(As[r][c]);
                af[mt][1] = f2tf32(As[r + 8][c]);
                af[mt][2] = f2tf32(As[r][c + 4]);
                af[mt][3] = f2tf32(As[r + 8][c + 4]);
            }
            uint32_t bf[4][2];
            #pragma unroll
            for (int nt = 0; nt < 4; nt++) {
                int col = warp_n * 32 + nt * 8 + grp;
                int kr = kb + tig;
                bf[nt][0] = f2tf32(Bs[kr][col]);
                bf[nt][1] = f2tf32(Bs[kr + 4][col]);
            }
            #pragma unroll
            for (int mt = 0; mt < 4; mt++)
                #pragma unroll
                for (int nt = 0; nt < 4; nt++) {
                    asm volatile(
                        "mma.sync.aligned.m16n8k8.row.col.f32.tf32.tf32.f32 "
                        "{%0,%1,%2,%3}, {%4,%5,%6,%7}, {%8,%9}, {%0,%1,%2,%3};"
                        : "+f"(acc[mt][nt][0]), "+f"(acc[mt][nt][1]),
                          "+f"(acc[mt][nt][2]), "+f"(acc[mt][nt][3])
                        : "r"(af[mt][0]), "r"(af[mt][1]), "r"(af[mt][2]), "r"(af[mt][3]),
                          "r"(bf[nt][0]), "r"(bf[nt][1]));
                }
        }
        __syncthreads();
    }

    // epilogue: row scale + fp16 store
    #pragma unroll
    for (int mt = 0; mt < 4; mt++) {
        int r0 = m0 + warp_m * 64 + mt * 16 + grp;
        int r1 = r0 + 8;
        float s0 = (r0 < M) ? scale[r0] : 0.f;
        float s1 = (r1 < M) ? scale[r1] : 0.f;
        #pragma unroll
        for (int nt = 0; nt < 4; nt++) {
            int col = warp_n * 32 + nt * 8 + tig * 2;
            if (r0 < M) {
                __half2 h = __floats2half2_rn(acc[mt][nt][0] * s0, acc[mt][nt][1] * s0);
                *(__half2*)&Y[(size_t)r0 * C + col] = h;
            }
            if (r1 < M) {
                __half2 h = __floats2half2_rn(acc[mt][nt][2] * s1, acc[mt][nt][3] * s1);
                *(__half2*)&Y[(size_t)r1 * C + col] = h;
            }
        }
    }
}

// ---------------- aggregation: HALF-warp per dst node, uint4 (16B) fp16 gather ----------------
__device__ __forceinline__ void add8(float* a, uint4 v) {
    __half2 h0 = *reinterpret_cast<const __half2*>(&v.x);
    __half2 h1 = *reinterpret_cast<const __half2*>(&v.y);
    __half2 h2 = *reinterpret_cast<const __half2*>(&v.z);
    __half2 h3 = *reinterpret_cast<const __half2*>(&v.w);
    float2 f0 = __half22float2(h0), f1 = __half22float2(h1);
    float2 f2 = __half22float2(h2), f3 = __half22float2(h3);
    a[0] += f0.x; a[1] += f0.y; a[2] += f1.x; a[3] += f1.y;
    a[4] += f2.x; a[5] += f2.y; a[6] += f3.x; a[7] += f3.y;
}

__global__ __launch_bounds__(256)
void k_agg(const __half* __restrict__ Y, __half* __restrict__ H,
           const float* __restrict__ bias) {
    int t = blockIdx.x * blockDim.x + threadIdx.x;
    int d = t >> 4;                 // 16 lanes per node
    if (d >= NN) return;
    int lane = t & 15;              // lane covers features [lane*8, lane*8+8)
    const uint4* Yv = (const uint4*)Y;   // 16 uint4 chunks per 128-feature row

    float acc[8] = {0.f, 0.f, 0.f, 0.f, 0.f, 0.f, 0.f, 0.f};
    add8(acc, Yv[(size_t)d * 16 + lane]);    // self loop
    int e = g_rowoff[d], end = g_rowoff[d + 1];

    for (; e + 4 <= end; e += 4) {
        int s0 = g_csr[e], s1 = g_csr[e + 1], s2 = g_csr[e + 2], s3 = g_csr[e + 3];
        uint4 v0 = Yv[(size_t)s0 * 16 + lane];
        uint4 v1 = Yv[(size_t)s1 * 16 + lane];
        uint4 v2 = Yv[(size_t)s2 * 16 + lane];
        uint4 v3 = Yv[(size_t)s3 * 16 + lane];
        add8(acc, v0); add8(acc, v1); add8(acc, v2); add8(acc, v3);
    }
    for (; e < end; e++) {
        add8(acc, Yv[(size_t)g_csr[e] * 16 + lane]);
    }

    float dv = g_dinv[d];
    float4 b0 = ((const float4*)bias)[lane * 2];
    float4 b1 = ((const float4*)bias)[lane * 2 + 1];
    float o[8];
    o[0] = fmaxf(fmaf(acc[0], dv, b0.x), 0.f);
    o[1] = fmaxf(fmaf(acc[1], dv, b0.y), 0.f);
    o[2] = fmaxf(fmaf(acc[2], dv, b0.z), 0.f);
    o[3] = fmaxf(fmaf(acc[3], dv, b0.w), 0.f);
    o[4] = fmaxf(fmaf(acc[4], dv, b1.x), 0.f);
    o[5] = fmaxf(fmaf(acc[5], dv, b1.y), 0.f);
    o[6] = fmaxf(fmaf(acc[6], dv, b1.z), 0.f);
    o[7] = fmaxf(fmaf(acc[7], dv, b1.w), 0.f);
    __half2 p0 = __floats2half2_rn(o[0], o[1]);
    __half2 p1 = __floats2half2_rn(o[2], o[3]);
    __half2 p2 = __floats2half2_rn(o[4], o[5]);
    __half2 p3 = __floats2half2_rn(o[6], o[7]);
    uint4 outv;
    outv.x = *reinterpret_cast<uint32_t*>(&p0);
    outv.y = *reinterpret_cast<uint32_t*>(&p1);
    outv.z = *reinterpret_cast<uint32_t*>(&p2);
    outv.w = *reinterpret_cast<uint32_t*>(&p3);
    ((uint4*)H)[(size_t)d * 16 + lane] = outv;
}

// ---------------- pooling: segmented partial sums over sorted batch ----------------
__global__ void k_pool(const __half* __restrict__ H,
                       const int* __restrict__ batch) {
    const int CH = 128;
    int f = threadIdx.x;
    int n0 = blockIdx.x * CH;
    if (n0 >= NN) return;
    int n1 = n0 + CH; if (n1 > NN) n1 = NN;

    int cur = batch[n0];
    float acc = 0.f, c = 0.f;
    for (int n = n0; n < n1; n++) {
        int g = batch[n];
        if (g != cur) {
            atomicAdd(&g_pool[cur * C + f], acc);
            if (f == 0) atomicAdd(&g_gcnt[cur], c);
            acc = 0.f; c = 0.f; cur = g;
        }
        acc += __half2float(H[(size_t)n * C + f]);
        c += 1.f;
    }
    atomicAdd(&g_pool[cur * C + f], acc);
    if (f == 0) atomicAdd(&g_gcnt[cur], c);
}

// ---------------- final linear ----------------
__global__ void k_final(const float* __restrict__ Wlin,
                        const float* __restrict__ blin,
                        float* __restrict__ out) {
    int t = threadIdx.x;
    if (t >= NG * OUTC) return;
    int g = t / OUTC, o = t % OUTC;
    float inv = 1.f / fmaxf(g_gcnt[g], 1.f);
    float s = blin[o];
    #pragma unroll 8
    for (int k = 0; k < C; k++)
        s = fmaf(g_pool[g * C + k] * inv, Wlin[k * OUTC + o], s);
    out[t] = s;
}

// ---------------- launch ----------------
extern "C" void kernel_launch(void* const* d_in, const int* in_sizes, int n_in,
                              void* d_out, int out_size) {
    const float* x     = (const float*)d_in[0];
    const int*   ei    = (const int*)d_in[1];
    const int*   batch = (const int*)d_in[2];
    const float* W1    = (const float*)d_in[3];
    const float* b1    = (const float*)d_in[4];
    const float* W2    = (const float*)d_in[5];
    const float* b2    = (const float*)d_in[6];
    const float* Wlin  = (const float*)d_in[7];
    const float* blin  = (const float*)d_in[8];
    float* out = (float*)d_out;

    const int* src = ei;
    const int* dst = ei + EE;

    __half *bufA, *bufB;
    float *dinv;
    cudaGetSymbolAddress((void**)&bufA, g_bufA);
    cudaGetSymbolAddress((void**)&bufB, g_bufB);
    cudaGetSymbolAddress((void**)&dinv, g_dinv);

    // side stream + events, created once on the first (non-capture) call.
    // Work enqueued is identical on every call.
    static cudaStream_t s_side = nullptr;
    static cudaEvent_t  ev_fork = nullptr, ev_join = nullptr;
    if (s_side == nullptr) {
        cudaStreamCreateWithFlags(&s_side, cudaStreamNonBlocking);
        cudaEventCreateWithFlags(&ev_fork, cudaEventDisableTiming);
        cudaEventCreateWithFlags(&ev_join, cudaEventDisableTiming);
    }

    // CSR prefix (serial: GEMM1 needs dinv from scan3)
    k_zero<<<256, 256>>>();
    k_hist<<<2048, 256>>>((const int4*)dst);
    k_scan1<<<SCAN_BLOCKS, 256>>>();
    k_scan2<<<1, 512>>>();
    k_scan3<<<SCAN_BLOCKS, 256>>>();

    const int gemm_blocks = (NN + 127) / 128;
    const int agg_blocks  = (NN * 16 + 255) / 256;

    // fork: k_fill (side stream) runs concurrently with GEMM1 (main stream)
    cudaEventRecord(ev_fork, 0);
    cudaStreamWaitEvent(s_side, ev_fork, 0);
    k_fill<<<2048, 256, 0, s_side>>>((const int4*)src, (const int4*)dst);
    k_gemm_tf32<float><<<gemm_blocks, 256>>>(x, W1, bufA, dinv, NN);
    cudaEventRecord(ev_join, s_side);
    cudaStreamWaitEvent(0, ev_join, 0);

    // layer 1 aggregation (needs both fill and GEMM1)
    k_agg<<<agg_blocks, 256>>>(bufA, bufB, b1);
    // layer 2
    k_gemm_tf32<__half><<<gemm_blocks, 256>>>(bufB, W2, bufA, dinv, NN);
    k_agg<<<agg_blocks, 256>>>(bufA, bufB, b2);

    // pooling + final linear
    k_pool<<<(NN + 127) / 128, 128>>>(bufB, batch);
    k_final<<<1, NG * OUTC>>>(Wlin, blin, out);
}